// round 15
// baseline (speedup 1.0000x reference)
#include <cuda_runtime.h>
#include <cuda_bf16.h>
#include <math.h>
#include <stdint.h>

// Problem constants
#define LEVEL   16
#define LENGTH  64
#define TOPK    2
#define SIZE    512
#define BATCH   32
#define NEG     (-1e8f)

#define LPOS    48
#define NCELLS  904
#define NIDX    768
#define ROWS1   49152
#define ROWS2   3072
#define KSPLIT  4
#define NCELLS_BL 1536
#define MAXCAND 16
#define MAXR    (NCELLS_BL * MAXCAND)   // 24576
#define GUARD   0.6f
#define HELEMS  (2 * 32 * 904 * 512)

// Output layout
#define OFF_H   0
#define OFF_S   1572864
#define OFF_N   1575936
#define OFF_LK  1579008
#define OFF_RK  1582080

// rescore kernel smem geometry (pipeline then reused as 128xTS tile)
#define A_PAD   20
#define B_PAD   136
#define A_BUF   (128 * A_PAD)
#define B_BUF   (16 * B_PAD)
#define TS      132
#define SMEM_R  (128 * TS * 4)          // 67584 B (> 2*(A_BUF+B_BUF)*4 = 37888)
// gemm2 LDSM tf32 kernel, 4-stage pipeline
#define TPAD    20
#define NST     4
#define ABYTES  (128 * TPAD * 4)
#define STAGE_BYTES (2 * ABYTES)
#define SMEM_PIPE (NST * STAGE_BYTES)
// gemm1 bf16 kernel
#define BROW    48
#define BTILE   (128 * BROW)
#define BSTG    (2 * BTILE)
#define NSTB    4
#define SMEM1   (128 * TS * 4)

// Scratch
__device__ float g_S[NCELLS_BL * 64];
__device__ __nv_bfloat16 g_Hbf[HELEMS];
__device__ __nv_bfloat16 g_matTbf[512 * 512];
__device__ float g_P[(size_t)KSPLIT * ROWS2 * 512];
__device__ float g_WcT[512 * 1024];
__device__ int   g_li[NIDX];
__device__ int   g_ri[NIDX];
__device__ int4  g_sel[ROWS2];
__device__ int   g_nrows;                // unique (bl,n,kl) rows
__device__ int   g_rows[MAXR];           // (bl<<5)|(n<<1)|kl
__device__ float g_spart[(size_t)MAXR * 8];   // [row][colblock(4)][kr(2)]
__device__ int   g_cz[MAXR];             // combo z per cell-contiguous slot
__device__ int   g_crow[MAXR];           // combo -> row index
__device__ int   g_cellbase[NCELLS_BL];
__device__ int   g_cellcnt[NCELLS_BL];
__device__ int   g_ncomb;

#define CP_ASYNC16(dst32, src) \
    asm volatile("cp.async.cg.shared.global [%0], [%1], 16;" :: "r"(dst32), "l"(src))
#define CP_COMMIT()  asm volatile("cp.async.commit_group;")
#define CP_WAIT0()   asm volatile("cp.async.wait_group 0;")
#define CP_WAIT2()   asm volatile("cp.async.wait_group 2;")

#define LDSM4(r0, r1, r2, r3, a) \
    asm volatile("ldmatrix.sync.aligned.m8n8.x4.shared.b16 {%0,%1,%2,%3}, [%4];" \
        : "=r"(r0), "=r"(r1), "=r"(r2), "=r"(r3) : "r"(a))

__device__ __forceinline__ void mma_tf32(float d[4],
        uint32_t a0, uint32_t a1, uint32_t a2, uint32_t a3,
        uint32_t b0, uint32_t b1) {
    asm volatile(
        "mma.sync.aligned.m16n8k8.row.col.f32.tf32.tf32.f32 "
        "{%0,%1,%2,%3}, {%4,%5,%6,%7}, {%8,%9}, {%0,%1,%2,%3};"
        : "+f"(d[0]), "+f"(d[1]), "+f"(d[2]), "+f"(d[3])
        : "r"(a0), "r"(a1), "r"(a2), "r"(a3), "r"(b0), "r"(b1));
}

__device__ __forceinline__ void mma_bf16(float d[4],
        uint32_t a0, uint32_t a1, uint32_t a2, uint32_t a3,
        uint32_t b0, uint32_t b1) {
    asm volatile(
        "mma.sync.aligned.m16n8k16.row.col.f32.bf16.bf16.f32 "
        "{%0,%1,%2,%3}, {%4,%5,%6,%7}, {%8,%9}, {%0,%1,%2,%3};"
        : "+f"(d[0]), "+f"(d[1]), "+f"(d[2]), "+f"(d[3])
        : "r"(a0), "r"(a1), "r"(a2), "r"(a3), "r"(b0), "r"(b1));
}

__device__ __forceinline__ float tf32_rna(float x) {
    uint32_t u;
    asm("cvt.rna.tf32.f32 %0, %1;" : "=r"(u) : "f"(x));
    return __uint_as_float(u);
}

// ---------------------------------------------------------------------------
// K0: index conversion + counter reset.
__global__ void conv_idx_kernel(const void* __restrict__ lraw,
                                const void* __restrict__ rraw) {
    if (blockIdx.x == 0 && threadIdx.x == 0) { g_nrows = 0; g_ncomb = 0; }
    const int* w = (const int*)lraw;
    bool is64 = (w[1] == 0 && w[2] == 64);
    int t = blockIdx.x * blockDim.x + threadIdx.x;
    if (t < NIDX) {
        if (is64) {
            g_li[t] = (int)((const long long*)lraw)[t];
            g_ri[t] = (int)((const long long*)rraw)[t];
        } else {
            g_li[t] = ((const int*)lraw)[t];
            g_ri[t] = ((const int*)rraw)[t];
        }
    }
}

// K0a: zero score accumulators.
__global__ void zero_scores_kernel(void) {
    int i = blockIdx.x * 256 + threadIdx.x;
    if (i < NCELLS_BL * 64) g_S[i] = 0.f;
}

// K0c: convert chart_h to bf16.
__global__ __launch_bounds__(256) void convert_h_kernel(const float* __restrict__ h) {
    size_t i = ((size_t)blockIdx.x * 256 + threadIdx.x) * 8;
    if (i >= HELEMS) return;
    float4 v0 = *(const float4*)(h + i);
    float4 v1 = *(const float4*)(h + i + 4);
    __nv_bfloat162 o[4];
    o[0] = __floats2bfloat162_rn(v0.x, v0.y);
    o[1] = __floats2bfloat162_rn(v0.z, v0.w);
    o[2] = __floats2bfloat162_rn(v1.x, v1.y);
    o[3] = __floats2bfloat162_rn(v1.z, v1.w);
    *(uint4*)(g_Hbf + i) = *(uint4*)o;
}

// K0d: transpose mat -> bf16 [n][k].
__global__ void transpose_mat_bf16_kernel(const float* __restrict__ src) {
    __shared__ float tile[32][33];
    int bx = blockIdx.x * 32;
    int by = blockIdx.y * 32;
    int tx = threadIdx.x, ty = threadIdx.y;
#pragma unroll
    for (int i = 0; i < 32; i += 8)
        tile[ty + i][tx] = src[(size_t)(by + ty + i) * 512 + bx + tx];
    __syncthreads();
#pragma unroll
    for (int i = 0; i < 32; i += 8)
        g_matTbf[(size_t)(bx + ty + i) * 512 + by + tx] =
            __float2bfloat16_rn(tile[tx][ty + i]);
}

// K0b: tiled transpose fp32 (WcT).
__global__ void transpose_kernel(const float* __restrict__ src,
                                 float* __restrict__ dst, int rows, int cols) {
    __shared__ float tile[32][33];
    int bx = blockIdx.x * 32;
    int by = blockIdx.y * 32;
    int tx = threadIdx.x, ty = threadIdx.y;
#pragma unroll
    for (int i = 0; i < 32; i += 8)
        tile[ty + i][tx] = src[(size_t)(by + ty + i) * cols + bx + tx];
    __syncthreads();
#pragma unroll
    for (int i = 0; i < 32; i += 8)
        dst[(size_t)(bx + ty + i) * rows + by + tx] = tile[tx][ty + i];
}

// ---------------------------------------------------------------------------
// K1: fused gemm1 (bf16) + scoring epilogue -> g_S atomics. (round-14 proven)
__global__ __launch_bounds__(256, 2) void gemm1_fused_kernel(
    const float* __restrict__ chart_h) {
    extern __shared__ float sm[];
    __shared__ const __nv_bfloat16* Arow[128];

    int tid  = threadIdx.x;
    int row0 = blockIdx.y * 128;
    int col0 = blockIdx.x * 128;

    if (tid < 128) {
        int r = row0 + tid;
        int k = r & 1;
        int t = r >> 1;
        int n = t & 15;
        int bl = t >> 4;
        int l = bl % LPOS, b = bl / LPOS;
        int cell = g_li[(l << 4) + n];
        Arow[tid] = g_Hbf + (((size_t)(k * BATCH + b)) * NCELLS + cell) * SIZE;
    }
    __syncthreads();

    int cr = tid >> 1, ch = tid & 1;
    const __nv_bfloat16* gA = Arow[cr] + ch * 8;
    const __nv_bfloat16* gB = g_matTbf + (size_t)(col0 + cr) * 512 + ch * 8;

    uint32_t base = (uint32_t)__cvta_generic_to_shared(sm);
    uint32_t cpA = base + cr * BROW + ch * 16;
    uint32_t cpB = base + BTILE + cr * BROW + ch * 16;

    int wid = tid >> 5, lane = tid & 31;
    int wm = wid >> 2, wn = wid & 3;
    int gid = lane >> 2, tig = lane & 3;
    int t4 = lane >> 3, lr = lane & 7;

    uint32_t aAddr[4], bAddr[2];
    {
        int arow_off = (t4 & 1) * 8 + lr;
        int ahalf = (t4 >> 1) * 16;
        int brow_off = (t4 >> 1) * 8 + lr;
        int bhalf = (t4 & 1) * 16;
#pragma unroll
        for (int mf = 0; mf < 4; mf++)
            aAddr[mf] = base + (wm * 64 + mf * 16 + arow_off) * BROW + ahalf;
#pragma unroll
        for (int p = 0; p < 2; p++)
            bAddr[p] = base + BTILE + (wn * 32 + p * 16 + brow_off) * BROW + bhalf;
    }

    float d[4][4][4];
#pragma unroll
    for (int mf = 0; mf < 4; mf++)
#pragma unroll
        for (int nf = 0; nf < 4; nf++)
#pragma unroll
            for (int c = 0; c < 4; c++) d[mf][nf][c] = 0.f;

#pragma unroll
    for (int s = 0; s < NSTB - 1; s++) {
        uint32_t so = s * BSTG;
        size_t go = (size_t)s * 16;
        CP_ASYNC16(cpA + so, gA + go);
        CP_ASYNC16(cpB + so, gB + go);
        CP_COMMIT();
    }

    for (int kt = 0; kt < 32; kt++) {
        CP_WAIT2();
        __syncthreads();
        int pf = kt + NSTB - 1;
        if (pf < 32) {
            uint32_t so = (pf & (NSTB - 1)) * BSTG;
            size_t go = (size_t)pf * 16;
            CP_ASYNC16(cpA + so, gA + go);
            CP_ASYNC16(cpB + so, gB + go);
        }
        CP_COMMIT();

        uint32_t soff = (kt & (NSTB - 1)) * BSTG;
        uint32_t a[4][4], bb[4][2];
#pragma unroll
        for (int mf = 0; mf < 4; mf++)
            LDSM4(a[mf][0], a[mf][1], a[mf][2], a[mf][3], aAddr[mf] + soff);
#pragma unroll
        for (int p = 0; p < 2; p++)
            LDSM4(bb[2 * p][0], bb[2 * p][1], bb[2 * p + 1][0], bb[2 * p + 1][1],
                  bAddr[p] + soff);
#pragma unroll
        for (int nf = 0; nf < 4; nf++)
#pragma unroll
            for (int mf = 0; mf < 4; mf++)
                mma_bf16(d[mf][nf], a[mf][0], a[mf][1], a[mf][2], a[mf][3],
                         bb[nf][0], bb[nf][1]);
    }

    __syncthreads();
#pragma unroll
    for (int mf = 0; mf < 4; mf++) {
        int lr0 = wm * 64 + mf * 16 + gid;
#pragma unroll
        for (int nf = 0; nf < 4; nf++) {
            int lc = wn * 32 + nf * 8 + tig * 2;
            *(float2*)&sm[lr0 * TS + lc]       = make_float2(d[mf][nf][0], d[mf][nf][1]);
            *(float2*)&sm[(lr0 + 8) * TS + lc] = make_float2(d[mf][nf][2], d[mf][nf][3]);
        }
    }
    __syncthreads();

    int pair0 = row0 >> 1;
#pragma unroll
    for (int gi = 0; gi < 8; gi++) {
        int g = wid * 8 + gi;
        int pair = pair0 + g;
        int bl = pair >> 4, n = pair & 15;
        int b = bl / LPOS, l = bl % LPOS;
        int rcell = g_ri[(l << 4) + n];
        const float* rh0 = chart_h + (((size_t)b) * NCELLS + rcell) * SIZE + col0;
        const float* rh1 = chart_h + (((size_t)(BATCH + b)) * NCELLS + rcell) * SIZE + col0;
        const float* u0 = &sm[(g * 2) * TS];
        const float* u1 = &sm[(g * 2 + 1) * TS];
        float a00 = 0.f, a01 = 0.f, a10 = 0.f, a11 = 0.f;
#pragma unroll
        for (int it = 0; it < 4; it++) {
            int i = lane + it * 32;
            float x0 = u0[i], x1 = u1[i], y0 = rh0[i], y1 = rh1[i];
            a00 += x0 * y0; a01 += x0 * y1;
            a10 += x1 * y0; a11 += x1 * y1;
        }
#pragma unroll
        for (int o = 16; o; o >>= 1) {
            a00 += __shfl_xor_sync(0xffffffffu, a00, o);
            a01 += __shfl_xor_sync(0xffffffffu, a01, o);
            a10 += __shfl_xor_sync(0xffffffffu, a10, o);
            a11 += __shfl_xor_sync(0xffffffffu, a11, o);
        }
        if (lane == 0) {
            float* sp = g_S + bl * 64 + n * 4;
            atomicAdd(sp + 0, a00);
            atomicAdd(sp + 1, a01);
            atomicAdd(sp + 2, a10);
            atomicAdd(sp + 3, a11);
        }
    }
}

// ---------------------------------------------------------------------------
// K2: nomination with (n,kl)-dedupe: emits unique lh rows + combo lists.
__global__ __launch_bounds__(256) void nominate_kernel(
    const float* __restrict__ chart_s) {
    int bl = blockIdx.x * 256 + threadIdx.x;
    if (bl >= NCELLS_BL) return;
    int b = bl / LPOS, l = bl % LPOS;

    float s[64];
#pragma unroll 4
    for (int n = 0; n < 16; n++) {
        int lcell = g_li[(l << 4) + n];
        int rcell = g_ri[(l << 4) + n];
        float ls0 = chart_s[(size_t)b * NCELLS + lcell];
        float ls1 = chart_s[(size_t)(BATCH + b) * NCELLS + lcell];
        float rs0 = chart_s[(size_t)b * NCELLS + rcell];
        float rs1 = chart_s[(size_t)(BATCH + b) * NCELLS + rcell];
        const float* sp = g_S + bl * 64 + n * 4;
        float v00 = sp[0] + ls0 + rs0, v01 = sp[1] + ls0 + rs1;
        float v10 = sp[2] + ls1 + rs0, v11 = sp[3] + ls1 + rs1;
        if (n == 0) { v10 = NEG; v11 = NEG; }   // penalty: catalan(1)=1
        s[n * 4 + 0] = v00; s[n * 4 + 1] = v01;
        s[n * 4 + 2] = v10; s[n * 4 + 3] = v11;
    }

    float b1 = -INFINITY; int i1 = 0;
    for (int z = 0; z < 64; z++) { float v = s[z]; if (v > b1) { b1 = v; i1 = z; } }
    float b2 = -INFINITY; int i2 = 0;
    for (int z = 0; z < 64; z++) {
        if (z == i1) continue;
        float v = s[z]; if (v > b2) { b2 = v; i2 = z; }
    }
    int cand[MAXCAND];
    int cnt = 0;
    cand[cnt++] = i1;
    cand[cnt++] = i2;
    float thr = b2 - GUARD;
    for (int z = 0; z < 64 && cnt < MAXCAND; z++) {
        if (z == i1 || z == i2) continue;
        if (s[z] >= thr) cand[cnt++] = z;
    }

    // dedupe by (n<<1)|kl == z>>1
    int ukey[MAXCAND], rowof[MAXCAND];
    int ucnt = 0;
    for (int c = 0; c < cnt; c++) {
        int key = cand[c] >> 1;
        int f = -1;
        for (int u = 0; u < ucnt; u++)
            if (ukey[u] == key) { f = u; break; }
        if (f < 0) { f = ucnt; ukey[ucnt++] = key; }
        rowof[c] = f;
    }
    int rbase = atomicAdd(&g_nrows, ucnt);
    int cbase = atomicAdd(&g_ncomb, cnt);
    g_cellbase[bl] = cbase;
    g_cellcnt[bl]  = cnt;
    for (int u = 0; u < ucnt; u++) g_rows[rbase + u] = (bl << 5) | ukey[u];
    for (int c = 0; c < cnt; c++) {
        g_cz[cbase + c]   = cand[c];
        g_crow[cbase + c] = rbase + rowof[c];
    }
}

// ---------------------------------------------------------------------------
// K3: 3xTF32 rescore GEMM with FUSED dot epilogue. Z tile stays in smem;
// per row writes partial dots (both kr) into g_spart[row][colblock][kr].
__global__ __launch_bounds__(256, 2) void rescore_gemm_kernel(
    const float* __restrict__ chart_h, const float* __restrict__ mat) {
    int nrows = g_nrows;
    if ((int)(blockIdx.y * 128) >= nrows) return;

    extern __shared__ float sm[];
    __shared__ const float* Arow[128];
    __shared__ const float* Brow0[128];
    __shared__ const float* Brow1[128];

    int tid  = threadIdx.x;
    int row0 = blockIdx.y * 128;
    int col0 = blockIdx.x * 128;

    if (tid < 128) {
        int r = row0 + tid;
        const float* p = chart_h;
        const float* q0 = chart_h;
        const float* q1 = chart_h;
        if (r < nrows) {
            int code = g_rows[r];
            int bl = code >> 5, n = (code >> 1) & 15, kl = code & 1;
            int b = bl / LPOS, l = bl % LPOS;
            int lcell = g_li[(l << 4) + n];
            int rcell = g_ri[(l << 4) + n];
            p  = chart_h + (((size_t)(kl * BATCH + b)) * NCELLS + lcell) * SIZE;
            q0 = chart_h + (((size_t)b) * NCELLS + rcell) * SIZE + col0;
            q1 = chart_h + (((size_t)(BATCH + b)) * NCELLS + rcell) * SIZE + col0;
        }
        Arow[tid] = p;
        Brow0[tid] = q0;
        Brow1[tid] = q1;
    }
    __syncthreads();

    int ar = tid >> 1,  aw = (tid & 1) * 8;
    int brr = tid >> 4, bw = (tid & 15) * 8;
    const float* gA = Arow[ar] + aw;
    const float* gB = mat + (size_t)brr * 512 + col0 + bw;

    uint32_t base = (uint32_t)__cvta_generic_to_shared(sm);
    uint32_t dA = base + (ar * A_PAD + aw) * 4;
    uint32_t dB = base + (2 * A_BUF + brr * B_PAD + bw) * 4;

    int wid = tid >> 5, lane = tid & 31;
    int wm = wid >> 2, wn = wid & 3;
    int gid = lane >> 2, tig = lane & 3;

    float d[4][4][4];
#pragma unroll
    for (int mf = 0; mf < 4; mf++)
#pragma unroll
        for (int nf = 0; nf < 4; nf++)
#pragma unroll
            for (int c = 0; c < 4; c++) d[mf][nf][c] = 0.f;

    CP_ASYNC16(dA, gA);
    CP_ASYNC16(dA + 16, gA + 4);
    CP_ASYNC16(dB, gB);
    CP_ASYNC16(dB + 16, gB + 4);
    CP_COMMIT();

    int buf = 0;
    for (int kt = 0; kt < 32; kt++) {
        CP_WAIT0();
        __syncthreads();
        if (kt < 31) {
            int nb = buf ^ 1;
            size_t goA = (size_t)(kt + 1) * 16;
            size_t goB = (size_t)(kt + 1) * 16 * 512;
            uint32_t nA = dA + (nb ? A_BUF * 4 : 0) - (buf ? A_BUF * 4 : 0);
            uint32_t nB = dB + (nb ? B_BUF * 4 : 0) - (buf ? B_BUF * 4 : 0);
            CP_ASYNC16(nA, gA + goA);
            CP_ASYNC16(nA + 16, gA + goA + 4);
            CP_ASYNC16(nB, gB + goB);
            CP_ASYNC16(nB + 16, gB + goB + 4);
            CP_COMMIT();
            dA = nA; dB = nB;
        }

        const float (*A)[A_PAD] = (const float (*)[A_PAD])(sm + buf * A_BUF);
        const float (*B)[B_PAD] = (const float (*)[B_PAD])(sm + 2 * A_BUF + buf * B_BUF);
#pragma unroll
        for (int kf = 0; kf < 2; kf++) {
            int k0 = kf * 8;
            uint32_t aH[4][4], aL[4][4];
#pragma unroll
            for (int mf = 0; mf < 4; mf++) {
                int m = wm * 64 + mf * 16 + gid;
                float v0 = A[m][k0 + tig];
                float v1 = A[m + 8][k0 + tig];
                float v2 = A[m][k0 + tig + 4];
                float v3 = A[m + 8][k0 + tig + 4];
                float h0 = tf32_rna(v0), h1 = tf32_rna(v1);
                float h2 = tf32_rna(v2), h3 = tf32_rna(v3);
                aH[mf][0] = __float_as_uint(h0); aL[mf][0] = __float_as_uint(tf32_rna(v0 - h0));
                aH[mf][1] = __float_as_uint(h1); aL[mf][1] = __float_as_uint(tf32_rna(v1 - h1));
                aH[mf][2] = __float_as_uint(h2); aL[mf][2] = __float_as_uint(tf32_rna(v2 - h2));
                aH[mf][3] = __float_as_uint(h3); aL[mf][3] = __float_as_uint(tf32_rna(v3 - h3));
            }
#pragma unroll
            for (int nf = 0; nf < 4; nf++) {
                int nn = wn * 32 + nf * 8 + gid;
                float w0 = B[k0 + tig][nn];
                float w1 = B[k0 + tig + 4][nn];
                float bh0f = tf32_rna(w0), bh1f = tf32_rna(w1);
                uint32_t bh0 = __float_as_uint(bh0f);
                uint32_t bh1 = __float_as_uint(bh1f);
                uint32_t bl0 = __float_as_uint(tf32_rna(w0 - bh0f));
                uint32_t bl1 = __float_as_uint(tf32_rna(w1 - bh1f));
#pragma unroll
                for (int mf = 0; mf < 4; mf++) {
                    mma_tf32(d[mf][nf], aH[mf][0], aH[mf][1], aH[mf][2], aH[mf][3], bl0, bl1);
                    mma_tf32(d[mf][nf], aL[mf][0], aL[mf][1], aL[mf][2], aL[mf][3], bh0, bh1);
                    mma_tf32(d[mf][nf], aH[mf][0], aH[mf][1], aH[mf][2], aH[mf][3], bh0, bh1);
                }
            }
        }
        buf ^= 1;
    }

    // ---- fused dot epilogue: stage Z tile, dot vs rh0/rh1, write partials ----
    __syncthreads();
#pragma unroll
    for (int mf = 0; mf < 4; mf++) {
        int lr0 = wm * 64 + mf * 16 + gid;
#pragma unroll
        for (int nf = 0; nf < 4; nf++) {
            int lc = wn * 32 + nf * 8 + tig * 2;
            *(float2*)&sm[lr0 * TS + lc]       = make_float2(d[mf][nf][0], d[mf][nf][1]);
            *(float2*)&sm[(lr0 + 8) * TS + lc] = make_float2(d[mf][nf][2], d[mf][nf][3]);
        }
    }
    __syncthreads();

#pragma unroll
    for (int gi = 0; gi < 16; gi++) {
        int lrow = wid * 16 + gi;
        int r = row0 + lrow;
        const float* u = &sm[lrow * TS];
        const float* y0 = Brow0[lrow];
        const float* y1 = Brow1[lrow];
        float a0 = 0.f, a1 = 0.f;
#pragma unroll
        for (int it = 0; it < 4; it++) {
            int i = lane + it * 32;
            float x = u[i];
            a0 += x * y0[i];
            a1 += x * y1[i];
        }
#pragma unroll
        for (int o = 16; o; o >>= 1) {
            a0 += __shfl_xor_sync(0xffffffffu, a0, o);
            a1 += __shfl_xor_sync(0xffffffffu, a1, o);
        }
        if (lane == 0 && r < nrows) {
            float* sp = g_spart + (size_t)r * 8 + blockIdx.x * 2;
            sp[0] = a0;
            sp[1] = a1;
        }
    }
}

// ---------------------------------------------------------------------------
// K5: per cell: sum partials (fixed order) + ls/rs, select exact top-2.
__global__ __launch_bounds__(256) void fix_select_kernel(
    const float* __restrict__ chart_s, float* __restrict__ out) {
    int bl = blockIdx.x * 256 + threadIdx.x;
    if (bl >= NCELLS_BL) return;
    int b = bl / LPOS, l = bl % LPOS;
    int cbase = g_cellbase[bl];
    int cnt   = g_cellcnt[bl];

    float s1 = -INFINITY, s2 = -INFINITY;
    int z1 = 64, z2 = 64;
    for (int c = 0; c < cnt; c++) {
        int z   = g_cz[cbase + c];
        int row = g_crow[cbase + c];
        int n = z >> 2, kl = (z >> 1) & 1, kr = z & 1;
        const float* sp = g_spart + (size_t)row * 8 + kr;
        float v = ((sp[0] + sp[2]) + (sp[4] + sp[6]));
        int lcell = g_li[(l << 4) + n];
        int rcell = g_ri[(l << 4) + n];
        v += chart_s[(size_t)(kl * BATCH + b) * NCELLS + lcell];
        v += chart_s[(size_t)(kr * BATCH + b) * NCELLS + rcell];
        if (v > s1 || (v == s1 && z < z1)) {
            s2 = s1; z2 = z1; s1 = v; z1 = z;
        } else if (v > s2 || (v == s2 && z < z2)) {
            s2 = v; z2 = z;
        }
    }
    int o = bl * 2;
    out[OFF_S  + o]     = s1;
    out[OFF_S  + o + 1] = s2;
    out[OFF_N  + o]     = (float)(z1 >> 2);
    out[OFF_N  + o + 1] = (float)(z2 >> 2);
    out[OFF_LK + o]     = (float)((z1 >> 1) & 1);
    out[OFF_LK + o + 1] = (float)((z2 >> 1) & 1);
    out[OFF_RK + o]     = (float)(z1 & 1);
    out[OFF_RK + o + 1] = (float)(z2 & 1);
    g_sel[o]     = make_int4(z1 >> 2, (z1 >> 1) & 1, z1 & 1, 0);
    g_sel[o + 1] = make_int4(z2 >> 2, (z2 >> 1) & 1, z2 & 1, 0);
}

// ---------------------------------------------------------------------------
// K6: compose GEMM, 1x tf32, LDSM + 4-stage pipeline, split-K=4.
__global__ __launch_bounds__(256, 2) void gemm2_mma_kernel(
    const float* __restrict__ chart_h) {
    extern __shared__ float sm[];
    __shared__ const float* Arow[128];

    int tid  = threadIdx.x;
    int row0 = blockIdx.y * 128;
    int col0 = blockIdx.x * 128;
    int ks   = blockIdx.z;
    int kbase = ks * 256;

    if (tid < 128) {
        int r = row0 + tid;
        int bl = r >> 1;
        int b = bl / LPOS, l = bl % LPOS;
        int4 sel = g_sel[r];
        const float* base;
        if (kbase < 512) {
            int lcell = g_li[(l << 4) + sel.x];
            base = chart_h + (((size_t)(sel.y * BATCH + b)) * NCELLS + lcell) * SIZE + kbase;
        } else {
            int rcell = g_ri[(l << 4) + sel.x];
            base = chart_h + (((size_t)(sel.z * BATCH + b)) * NCELLS + rcell) * SIZE + (kbase - 512);
        }
        Arow[tid] = base;
    }
    __syncthreads();

    int cr = tid >> 1, cw = (tid & 1) * 8;
    const float* gA = Arow[cr] + cw;
    const float* gB = g_WcT + (size_t)(col0 + cr) * 1024 + kbase + cw;

    uint32_t base = (uint32_t)__cvta_generic_to_shared(sm);
    uint32_t cpA = base + (cr * TPAD + cw) * 4;
    uint32_t cpB = base + ABYTES + (cr * TPAD + cw) * 4;

    int wid = tid >> 5, lane = tid & 31;
    int wm = wid >> 2, wn = wid & 3;
    int gid = lane >> 2, tig = lane & 3;
    int t4 = lane >> 3, lr = lane & 7;

    uint32_t aAddr[4], bAddr[2];
    {
        int arow_off = (t4 & 1) * 8 + lr, acol = (t4 >> 1) * 4;
        int brow_off = ((t4 >> 1) * 8) + lr, bcol = (t4 & 1) * 4;
#pragma unroll
        for (int mf = 0; mf < 4; mf++)
            aAddr[mf] = base + ((wm * 64 + mf * 16 + arow_off) * TPAD + acol) * 4;
#pragma unroll
        for (int p = 0; p < 2; p++)
            bAddr[p] = base + ABYTES + ((wn * 32 + p * 16 + brow_off) * TPAD + bcol) * 4;
    }

    float d[4][4][4];
#pragma unroll
    for (int mf = 0; mf < 4; mf++)
#pragma unroll
        for (int nf = 0; nf < 4; nf++)
#pragma unroll
            for (int c = 0; c < 4; c++) d[mf][nf][c] = 0.f;

#pragma unroll
    for (int s = 0; s < NST - 1; s++) {
        uint32_t so = s * STAGE_BYTES;
        size_t go = (size_t)s * 16;
        CP_ASYNC16(cpA + so, gA + go);
        CP_ASYNC16(cpA + so + 16, gA + go + 4);
        CP_ASYNC16(cpB + so, gB + go);
        CP_ASYNC16(cpB + so + 16, gB + go + 4);
        CP_COMMIT();
    }

    for (int kt = 0; kt < 16; kt++) {
        CP_WAIT2();
        __syncthreads();
        int pf = kt + NST - 1;
        if (pf < 16) {
            uint32_t so = (pf & (NST - 1)) * STAGE_BYTES;
            size_t go = (size_t)pf * 16;
            CP_ASYNC16(cpA + so, gA + go);
            CP_ASYNC16(cpA + so + 16, gA + go + 4);
            CP_ASYNC16(cpB + so, gB + go);
            CP_ASYNC16(cpB + so + 16, gB + go + 4);
        }
        CP_COMMIT();

        uint32_t soff = (kt & (NST - 1)) * STAGE_BYTES;
#pragma unroll
        for (int kf = 0; kf < 2; kf++) {
            uint32_t koff = soff + kf * 32;
            uint32_t a[4][4], bb[4][2];
#pragma unroll
            for (int mf = 0; mf < 4; mf++)
                LDSM4(a[mf][0], a[mf][1], a[mf][2], a[mf][3], aAddr[mf] + koff);
#pragma unroll
            for (int p = 0; p < 2; p++)
                LDSM4(bb[2 * p][0], bb[2 * p][1], bb[2 * p + 1][0], bb[2 * p + 1][1],
                      bAddr[p] + koff);
#pragma unroll
            for (int nf = 0; nf < 4; nf++)
#pragma unroll
                for (int mf = 0; mf < 4; mf++)
                    mma_tf32(d[mf][nf], a[mf][0], a[mf][1], a[mf][2], a[mf][3],
                             bb[nf][0], bb[nf][1]);
        }
    }

#pragma unroll
    for (int mf = 0; mf < 4; mf++) {
        int rA = row0 + wm * 64 + mf * 16 + gid;
#pragma unroll
        for (int nf = 0; nf < 4; nf++) {
            int cA = col0 + wn * 32 + nf * 8 + tig * 2;
            float* p = g_P + ((size_t)ks * ROWS2 + rA) * 512 + cA;
            *(float2*)p                = make_float2(d[mf][nf][0], d[mf][nf][1]);
            *(float2*)(p + 8 * 512)    = make_float2(d[mf][nf][2], d[mf][nf][3]);
        }
    }
}

// ---------------------------------------------------------------------------
// K7: combine split-K partials + bias + tanh + unit-norm, write topk_h.
__global__ __launch_bounds__(256) void combine_normalize_kernel(
    const float* __restrict__ bc, float* __restrict__ out) {
    int r = blockIdx.x;
    int t = threadIdx.x;
    const float* p = g_P + (size_t)r * 512;
    const size_t stride = (size_t)ROWS2 * 512;

    float v0 = bc[t]       + p[t]       + p[t + stride]       + p[t + 2*stride]       + p[t + 3*stride];
    float v1 = bc[t + 256] + p[t + 256] + p[t + 256 + stride] + p[t + 256 + 2*stride] + p[t + 256 + 3*stride];
    v0 = tanhf(v0);
    v1 = tanhf(v1);

    float ss = v0 * v0 + v1 * v1;
#pragma unroll
    for (int o = 16; o; o >>= 1) ss += __shfl_xor_sync(0xffffffffu, ss, o);
    __shared__ float red[8];
    __shared__ float s_inv;
    if ((t & 31) == 0) red[t >> 5] = ss;
    __syncthreads();
    if (t == 0) {
        float x = 0.f;
#pragma unroll
        for (int i = 0; i < 8; i++) x += red[i];
        s_inv = 1.0f / sqrtf(x);
    }
    __syncthreads();
    float inv = s_inv;
    out[OFF_H + (size_t)r * 512 + t]       = v0 * inv;
    out[OFF_H + (size_t)r * 512 + t + 256] = v1 * inv;
}

// ---------------------------------------------------------------------------
extern "C" void kernel_launch(void* const* d_in, const int* in_sizes, int n_in,
                              void* d_out, int out_size) {
    const float* chart_h = (const float*)d_in[0];
    const float* chart_s = (const float*)d_in[1];
    const void*  l_index = d_in[2];
    const void*  r_index = d_in[3];
    const float* mat     = (const float*)d_in[4];
    const float* Wc      = (const float*)d_in[5];
    const float* bc      = (const float*)d_in[6];
    float* out = (float*)d_out;

    float* WcT;  cudaGetSymbolAddress((void**)&WcT,  g_WcT);

    cudaFuncSetAttribute(gemm1_fused_kernel,
                         cudaFuncAttributeMaxDynamicSharedMemorySize, SMEM1);
    cudaFuncSetAttribute(rescore_gemm_kernel,
                         cudaFuncAttributeMaxDynamicSharedMemorySize, SMEM_R);
    cudaFuncSetAttribute(gemm2_mma_kernel,
                         cudaFuncAttributeMaxDynamicSharedMemorySize, SMEM_PIPE);

    conv_idx_kernel<<<3, 256>>>(l_index, r_index);
    zero_scores_kernel<<<(NCELLS_BL * 64 + 255) / 256, 256>>>();
    convert_h_kernel<<<(HELEMS / 8 + 255) / 256, 256>>>(chart_h);
    transpose_mat_bf16_kernel<<<dim3(16, 16), dim3(32, 8)>>>(mat);
    transpose_kernel<<<dim3(16, 32), dim3(32, 8)>>>(Wc, WcT, 1024, 512);
    gemm1_fused_kernel<<<dim3(4, ROWS1 / 128), 256, SMEM1>>>(chart_h);
    nominate_kernel<<<(NCELLS_BL + 255) / 256, 256>>>(chart_s);
    rescore_gemm_kernel<<<dim3(4, MAXR / 128), 256, SMEM_R>>>(chart_h, mat);
    fix_select_kernel<<<6, 256>>>(chart_s, out);
    gemm2_mma_kernel<<<dim3(4, ROWS2 / 128, KSPLIT), 256, SMEM_PIPE>>>(chart_h);
    combine_normalize_kernel<<<ROWS2, 256>>>(bc, out);
}

// round 16
// speedup vs baseline: 1.0453x; 1.0453x over previous
#include <cuda_runtime.h>
#include <cuda_bf16.h>
#include <math.h>
#include <stdint.h>

// Problem constants
#define LEVEL   16
#define LENGTH  64
#define TOPK    2
#define SIZE    512
#define BATCH   32
#define NEG     (-1e8f)

#define LPOS    48
#define NCELLS  904
#define NIDX    768
#define ROWS1   49152
#define ROWS2   3072
#define KSPLIT  4
#define NCELLS_BL 1536
#define MAXCAND 16
#define MAXR    (NCELLS_BL * MAXCAND)
#define GUARD   0.7f
#define HELEMS  (2 * 32 * 904 * 512)

// Output layout
#define OFF_H   0
#define OFF_S   1572864
#define OFF_N   1575936
#define OFF_LK  1579008
#define OFF_RK  1582080

// rescore kernel smem geometry
#define A_PAD   20
#define B_PAD   136
#define A_BUF   (128 * A_PAD)
#define B_BUF   (16 * B_PAD)
#define TS      132
#define SMEM_R  (128 * TS * 4)
// gemm2 LDSM tf32 kernel
#define TPAD    20
#define NST     4
#define ABYTES  (128 * TPAD * 4)
#define STAGE_BYTES (2 * ABYTES)
#define SMEM_PIPE (NST * STAGE_BYTES)
// gemm1 bf16 kernel
#define BROW    48
#define BTILE   (128 * BROW)
#define BSTG    (2 * BTILE)
#define NSTB    4
#define SMEM1   (128 * TS * 4)

// prep kernel block ranges
#define NB_CONV  14464                  // HELEMS/8/256
#define NB_TMAT  256                    // 16x16
#define NB_TWC   512                    // 16x32
#define NB_ZERO  384                    // 98304/256
#define NB_IDX   3
#define NB_PREP  (NB_CONV + NB_TMAT + NB_TWC + NB_ZERO + NB_IDX)

// Scratch
__device__ float g_S[NCELLS_BL * 64];
__device__ __nv_bfloat16 g_Hbf[HELEMS];
__device__ __nv_bfloat16 g_matTbf[512 * 512];
__device__ float g_P[(size_t)KSPLIT * ROWS2 * 512];
__device__ float g_WcT[512 * 1024];
__device__ int   g_li[NIDX];
__device__ int   g_ri[NIDX];
__device__ int4  g_sel[ROWS2];
__device__ int   g_nrows;
__device__ int   g_rows[MAXR];
__device__ float g_spart[(size_t)MAXR * 8];
__device__ int   g_cz[MAXR];
__device__ int   g_crow[MAXR];
__device__ int   g_cellbase[NCELLS_BL];
__device__ int   g_cellcnt[NCELLS_BL];
__device__ int   g_ncomb;

#define CP_ASYNC16(dst32, src) \
    asm volatile("cp.async.cg.shared.global [%0], [%1], 16;" :: "r"(dst32), "l"(src))
#define CP_COMMIT()  asm volatile("cp.async.commit_group;")
#define CP_WAIT0()   asm volatile("cp.async.wait_group 0;")
#define CP_WAIT2()   asm volatile("cp.async.wait_group 2;")

#define LDSM4(r0, r1, r2, r3, a) \
    asm volatile("ldmatrix.sync.aligned.m8n8.x4.shared.b16 {%0,%1,%2,%3}, [%4];" \
        : "=r"(r0), "=r"(r1), "=r"(r2), "=r"(r3) : "r"(a))

__device__ __forceinline__ void mma_tf32(float d[4],
        uint32_t a0, uint32_t a1, uint32_t a2, uint32_t a3,
        uint32_t b0, uint32_t b1) {
    asm volatile(
        "mma.sync.aligned.m16n8k8.row.col.f32.tf32.tf32.f32 "
        "{%0,%1,%2,%3}, {%4,%5,%6,%7}, {%8,%9}, {%0,%1,%2,%3};"
        : "+f"(d[0]), "+f"(d[1]), "+f"(d[2]), "+f"(d[3])
        : "r"(a0), "r"(a1), "r"(a2), "r"(a3), "r"(b0), "r"(b1));
}

__device__ __forceinline__ void mma_bf16(float d[4],
        uint32_t a0, uint32_t a1, uint32_t a2, uint32_t a3,
        uint32_t b0, uint32_t b1) {
    asm volatile(
        "mma.sync.aligned.m16n8k16.row.col.f32.bf16.bf16.f32 "
        "{%0,%1,%2,%3}, {%4,%5,%6,%7}, {%8,%9}, {%0,%1,%2,%3};"
        : "+f"(d[0]), "+f"(d[1]), "+f"(d[2]), "+f"(d[3])
        : "r"(a0), "r"(a1), "r"(a2), "r"(a3), "r"(b0), "r"(b1));
}

__device__ __forceinline__ float tf32_rna(float x) {
    uint32_t u;
    asm("cvt.rna.tf32.f32 %0, %1;" : "=r"(u) : "f"(x));
    return __uint_as_float(u);
}

// ---------------------------------------------------------------------------
// K0: ALL preprocessing in one kernel (jobs run concurrently across SMs):
// convert chart_h->bf16 | mat->bf16^T | Wc->f32^T | zero g_S | idx convert.
__global__ __launch_bounds__(256) void prep_kernel(
    const float* __restrict__ h, const float* __restrict__ mat,
    const float* __restrict__ Wc, const void* __restrict__ lraw,
    const void* __restrict__ rraw) {
    __shared__ float tile[32][33];
    int bid = blockIdx.x;
    int tid = threadIdx.x;

    if (bid < NB_CONV) {
        size_t i = ((size_t)bid * 256 + tid) * 8;
        float4 v0 = *(const float4*)(h + i);
        float4 v1 = *(const float4*)(h + i + 4);
        __nv_bfloat162 o[4];
        o[0] = __floats2bfloat162_rn(v0.x, v0.y);
        o[1] = __floats2bfloat162_rn(v0.z, v0.w);
        o[2] = __floats2bfloat162_rn(v1.x, v1.y);
        o[3] = __floats2bfloat162_rn(v1.z, v1.w);
        *(uint4*)(g_Hbf + i) = *(uint4*)o;
        return;
    }
    bid -= NB_CONV;
    if (bid < NB_TMAT) {
        int bx = (bid & 15) * 32, by = (bid >> 4) * 32;
        int tx = tid & 31, ty = tid >> 5;
#pragma unroll
        for (int i = 0; i < 32; i += 8)
            tile[ty + i][tx] = mat[(size_t)(by + ty + i) * 512 + bx + tx];
        __syncthreads();
#pragma unroll
        for (int i = 0; i < 32; i += 8)
            g_matTbf[(size_t)(bx + ty + i) * 512 + by + tx] =
                __float2bfloat16_rn(tile[tx][ty + i]);
        return;
    }
    bid -= NB_TMAT;
    if (bid < NB_TWC) {
        int bx = (bid & 15) * 32, by = (bid >> 4) * 32;   // cols 512, rows 1024
        int tx = tid & 31, ty = tid >> 5;
#pragma unroll
        for (int i = 0; i < 32; i += 8)
            tile[ty + i][tx] = Wc[(size_t)(by + ty + i) * 512 + bx + tx];
        __syncthreads();
#pragma unroll
        for (int i = 0; i < 32; i += 8)
            g_WcT[(size_t)(bx + ty + i) * 1024 + by + tx] = tile[tx][ty + i];
        return;
    }
    bid -= NB_TWC;
    if (bid < NB_ZERO) {
        g_S[bid * 256 + tid] = 0.f;
        return;
    }
    bid -= NB_ZERO;
    {
        if (bid == 0 && tid == 0) { g_nrows = 0; g_ncomb = 0; }
        const int* w = (const int*)lraw;
        bool is64 = (w[1] == 0 && w[2] == 64);
        int t = bid * 256 + tid;
        if (t < NIDX) {
            if (is64) {
                g_li[t] = (int)((const long long*)lraw)[t];
                g_ri[t] = (int)((const long long*)rraw)[t];
            } else {
                g_li[t] = ((const int*)lraw)[t];
                g_ri[t] = ((const int*)rraw)[t];
            }
        }
    }
}

// ---------------------------------------------------------------------------
// K1: fused gemm1 (bf16) + scoring epilogue (rh read as bf16) -> g_S atomics.
__global__ __launch_bounds__(256, 2) void gemm1_fused_kernel(void) {
    extern __shared__ float sm[];
    __shared__ const __nv_bfloat16* Arow[128];

    int tid  = threadIdx.x;
    int row0 = blockIdx.y * 128;
    int col0 = blockIdx.x * 128;

    if (tid < 128) {
        int r = row0 + tid;
        int k = r & 1;
        int t = r >> 1;
        int n = t & 15;
        int bl = t >> 4;
        int l = bl % LPOS, b = bl / LPOS;
        int cell = g_li[(l << 4) + n];
        Arow[tid] = g_Hbf + (((size_t)(k * BATCH + b)) * NCELLS + cell) * SIZE;
    }
    __syncthreads();

    int cr = tid >> 1, ch = tid & 1;
    const __nv_bfloat16* gA = Arow[cr] + ch * 8;
    const __nv_bfloat16* gB = g_matTbf + (size_t)(col0 + cr) * 512 + ch * 8;

    uint32_t base = (uint32_t)__cvta_generic_to_shared(sm);
    uint32_t cpA = base + cr * BROW + ch * 16;
    uint32_t cpB = base + BTILE + cr * BROW + ch * 16;

    int wid = tid >> 5, lane = tid & 31;
    int wm = wid >> 2, wn = wid & 3;
    int gid = lane >> 2, tig = lane & 3;
    int t4 = lane >> 3, lr = lane & 7;

    uint32_t aAddr[4], bAddr[2];
    {
        int arow_off = (t4 & 1) * 8 + lr;
        int ahalf = (t4 >> 1) * 16;
        int brow_off = (t4 >> 1) * 8 + lr;
        int bhalf = (t4 & 1) * 16;
#pragma unroll
        for (int mf = 0; mf < 4; mf++)
            aAddr[mf] = base + (wm * 64 + mf * 16 + arow_off) * BROW + ahalf;
#pragma unroll
        for (int p = 0; p < 2; p++)
            bAddr[p] = base + BTILE + (wn * 32 + p * 16 + brow_off) * BROW + bhalf;
    }

    float d[4][4][4];
#pragma unroll
    for (int mf = 0; mf < 4; mf++)
#pragma unroll
        for (int nf = 0; nf < 4; nf++)
#pragma unroll
            for (int c = 0; c < 4; c++) d[mf][nf][c] = 0.f;

#pragma unroll
    for (int s = 0; s < NSTB - 1; s++) {
        uint32_t so = s * BSTG;
        size_t go = (size_t)s * 16;
        CP_ASYNC16(cpA + so, gA + go);
        CP_ASYNC16(cpB + so, gB + go);
        CP_COMMIT();
    }

    for (int kt = 0; kt < 32; kt++) {
        CP_WAIT2();
        __syncthreads();
        int pf = kt + NSTB - 1;
        if (pf < 32) {
            uint32_t so = (pf & (NSTB - 1)) * BSTG;
            size_t go = (size_t)pf * 16;
            CP_ASYNC16(cpA + so, gA + go);
            CP_ASYNC16(cpB + so, gB + go);
        }
        CP_COMMIT();

        uint32_t soff = (kt & (NSTB - 1)) * BSTG;
        uint32_t a[4][4], bb[4][2];
#pragma unroll
        for (int mf = 0; mf < 4; mf++)
            LDSM4(a[mf][0], a[mf][1], a[mf][2], a[mf][3], aAddr[mf] + soff);
#pragma unroll
        for (int p = 0; p < 2; p++)
            LDSM4(bb[2 * p][0], bb[2 * p][1], bb[2 * p + 1][0], bb[2 * p + 1][1],
                  bAddr[p] + soff);
#pragma unroll
        for (int nf = 0; nf < 4; nf++)
#pragma unroll
            for (int mf = 0; mf < 4; mf++)
                mma_bf16(d[mf][nf], a[mf][0], a[mf][1], a[mf][2], a[mf][3],
                         bb[nf][0], bb[nf][1]);
    }

    __syncthreads();
#pragma unroll
    for (int mf = 0; mf < 4; mf++) {
        int lr0 = wm * 64 + mf * 16 + gid;
#pragma unroll
        for (int nf = 0; nf < 4; nf++) {
            int lc = wn * 32 + nf * 8 + tig * 2;
            *(float2*)&sm[lr0 * TS + lc]       = make_float2(d[mf][nf][0], d[mf][nf][1]);
            *(float2*)&sm[(lr0 + 8) * TS + lc] = make_float2(d[mf][nf][2], d[mf][nf][3]);
        }
    }
    __syncthreads();

    int pair0 = row0 >> 1;
#pragma unroll
    for (int gi = 0; gi < 8; gi++) {
        int g = wid * 8 + gi;
        int pair = pair0 + g;
        int bl = pair >> 4, n = pair & 15;
        int b = bl / LPOS, l = bl % LPOS;
        int rcell = g_ri[(l << 4) + n];
        const __nv_bfloat16* rh0 = g_Hbf + (((size_t)b) * NCELLS + rcell) * SIZE + col0;
        const __nv_bfloat16* rh1 = g_Hbf + (((size_t)(BATCH + b)) * NCELLS + rcell) * SIZE + col0;
        const float* u0 = &sm[(g * 2) * TS];
        const float* u1 = &sm[(g * 2 + 1) * TS];
        float a00 = 0.f, a01 = 0.f, a10 = 0.f, a11 = 0.f;
#pragma unroll
        for (int it = 0; it < 4; it++) {
            int i = lane + it * 32;
            float x0 = u0[i], x1 = u1[i];
            float y0 = __bfloat162float(rh0[i]);
            float y1 = __bfloat162float(rh1[i]);
            a00 += x0 * y0; a01 += x0 * y1;
            a10 += x1 * y0; a11 += x1 * y1;
        }
#pragma unroll
        for (int o = 16; o; o >>= 1) {
            a00 += __shfl_xor_sync(0xffffffffu, a00, o);
            a01 += __shfl_xor_sync(0xffffffffu, a01, o);
            a10 += __shfl_xor_sync(0xffffffffu, a10, o);
            a11 += __shfl_xor_sync(0xffffffffu, a11, o);
        }
        if (lane == 0) {
            float* sp = g_S + bl * 64 + n * 4;
            atomicAdd(sp + 0, a00);
            atomicAdd(sp + 1, a01);
            atomicAdd(sp + 2, a10);
            atomicAdd(sp + 3, a11);
        }
    }
}

// ---------------------------------------------------------------------------
// K2: nomination with (n,kl)-dedupe.
__global__ __launch_bounds__(256) void nominate_kernel(
    const float* __restrict__ chart_s) {
    int bl = blockIdx.x * 256 + threadIdx.x;
    if (bl >= NCELLS_BL) return;
    int b = bl / LPOS, l = bl % LPOS;

    float s[64];
#pragma unroll 4
    for (int n = 0; n < 16; n++) {
        int lcell = g_li[(l << 4) + n];
        int rcell = g_ri[(l << 4) + n];
        float ls0 = chart_s[(size_t)b * NCELLS + lcell];
        float ls1 = chart_s[(size_t)(BATCH + b) * NCELLS + lcell];
        float rs0 = chart_s[(size_t)b * NCELLS + rcell];
        float rs1 = chart_s[(size_t)(BATCH + b) * NCELLS + rcell];
        const float* sp = g_S + bl * 64 + n * 4;
        float v00 = sp[0] + ls0 + rs0, v01 = sp[1] + ls0 + rs1;
        float v10 = sp[2] + ls1 + rs0, v11 = sp[3] + ls1 + rs1;
        if (n == 0) { v10 = NEG; v11 = NEG; }   // penalty: catalan(1)=1
        s[n * 4 + 0] = v00; s[n * 4 + 1] = v01;
        s[n * 4 + 2] = v10; s[n * 4 + 3] = v11;
    }

    float b1 = -INFINITY; int i1 = 0;
    for (int z = 0; z < 64; z++) { float v = s[z]; if (v > b1) { b1 = v; i1 = z; } }
    float b2 = -INFINITY; int i2 = 0;
    for (int z = 0; z < 64; z++) {
        if (z == i1) continue;
        float v = s[z]; if (v > b2) { b2 = v; i2 = z; }
    }
    int cand[MAXCAND];
    int cnt = 0;
    cand[cnt++] = i1;
    cand[cnt++] = i2;
    float thr = b2 - GUARD;
    for (int z = 0; z < 64 && cnt < MAXCAND; z++) {
        if (z == i1 || z == i2) continue;
        if (s[z] >= thr) cand[cnt++] = z;
    }

    int ukey[MAXCAND], rowof[MAXCAND];
    int ucnt = 0;
    for (int c = 0; c < cnt; c++) {
        int key = cand[c] >> 1;
        int f = -1;
        for (int u = 0; u < ucnt; u++)
            if (ukey[u] == key) { f = u; break; }
        if (f < 0) { f = ucnt; ukey[ucnt++] = key; }
        rowof[c] = f;
    }
    int rbase = atomicAdd(&g_nrows, ucnt);
    int cbase = atomicAdd(&g_ncomb, cnt);
    g_cellbase[bl] = cbase;
    g_cellcnt[bl]  = cnt;
    for (int u = 0; u < ucnt; u++) g_rows[rbase + u] = (bl << 5) | ukey[u];
    for (int c = 0; c < cnt; c++) {
        g_cz[cbase + c]   = cand[c];
        g_crow[cbase + c] = rbase + rowof[c];
    }
}

// ---------------------------------------------------------------------------
// K3: 3xTF32 rescore GEMM with fused dot epilogue (exact fp32 rh).
__global__ __launch_bounds__(256, 2) void rescore_gemm_kernel(
    const float* __restrict__ chart_h, const float* __restrict__ mat) {
    int nrows = g_nrows;
    if ((int)(blockIdx.y * 128) >= nrows) return;

    extern __shared__ float sm[];
    __shared__ const float* Arow[128];
    __shared__ const float* Brow0[128];
    __shared__ const float* Brow1[128];

    int tid  = threadIdx.x;
    int row0 = blockIdx.y * 128;
    int col0 = blockIdx.x * 128;

    if (tid < 128) {
        int r = row0 + tid;
        const float* p = chart_h;
        const float* q0 = chart_h;
        const float* q1 = chart_h;
        if (r < nrows) {
            int code = g_rows[r];
            int bl = code >> 5, n = (code >> 1) & 15, kl = code & 1;
            int b = bl / LPOS, l = bl % LPOS;
            int lcell = g_li[(l << 4) + n];
            int rcell = g_ri[(l << 4) + n];
            p  = chart_h + (((size_t)(kl * BATCH + b)) * NCELLS + lcell) * SIZE;
            q0 = chart_h + (((size_t)b) * NCELLS + rcell) * SIZE + col0;
            q1 = chart_h + (((size_t)(BATCH + b)) * NCELLS + rcell) * SIZE + col0;
        }
        Arow[tid] = p;
        Brow0[tid] = q0;
        Brow1[tid] = q1;
    }
    __syncthreads();

    int ar = tid >> 1,  aw = (tid & 1) * 8;
    int brr = tid >> 4, bw = (tid & 15) * 8;
    const float* gA = Arow[ar] + aw;
    const float* gB = mat + (size_t)brr * 512 + col0 + bw;

    uint32_t base = (uint32_t)__cvta_generic_to_shared(sm);
    uint32_t dA = base + (ar * A_PAD + aw) * 4;
    uint32_t dB = base + (2 * A_BUF + brr * B_PAD + bw) * 4;

    int wid = tid >> 5, lane = tid & 31;
    int wm = wid >> 2, wn = wid & 3;
    int gid = lane >> 2, tig = lane & 3;

    float d[4][4][4];
#pragma unroll
    for (int mf = 0; mf < 4; mf++)
#pragma unroll
        for (int nf = 0; nf < 4; nf++)
#pragma unroll
            for (int c = 0; c < 4; c++) d[mf][nf][c] = 0.f;

    CP_ASYNC16(dA, gA);
    CP_ASYNC16(dA + 16, gA + 4);
    CP_ASYNC16(dB, gB);
    CP_ASYNC16(dB + 16, gB + 4);
    CP_COMMIT();

    int buf = 0;
    for (int kt = 0; kt < 32; kt++) {
        CP_WAIT0();
        __syncthreads();
        if (kt < 31) {
            int nb = buf ^ 1;
            size_t goA = (size_t)(kt + 1) * 16;
            size_t goB = (size_t)(kt + 1) * 16 * 512;
            uint32_t nA = dA + (nb ? A_BUF * 4 : 0) - (buf ? A_BUF * 4 : 0);
            uint32_t nB = dB + (nb ? B_BUF * 4 : 0) - (buf ? B_BUF * 4 : 0);
            CP_ASYNC16(nA, gA + goA);
            CP_ASYNC16(nA + 16, gA + goA + 4);
            CP_ASYNC16(nB, gB + goB);
            CP_ASYNC16(nB + 16, gB + goB + 4);
            CP_COMMIT();
            dA = nA; dB = nB;
        }

        const float (*A)[A_PAD] = (const float (*)[A_PAD])(sm + buf * A_BUF);
        const float (*B)[B_PAD] = (const float (*)[B_PAD])(sm + 2 * A_BUF + buf * B_BUF);
#pragma unroll
        for (int kf = 0; kf < 2; kf++) {
            int k0 = kf * 8;
            uint32_t aH[4][4], aL[4][4];
#pragma unroll
            for (int mf = 0; mf < 4; mf++) {
                int m = wm * 64 + mf * 16 + gid;
                float v0 = A[m][k0 + tig];
                float v1 = A[m + 8][k0 + tig];
                float v2 = A[m][k0 + tig + 4];
                float v3 = A[m + 8][k0 + tig + 4];
                float h0 = tf32_rna(v0), h1 = tf32_rna(v1);
                float h2 = tf32_rna(v2), h3 = tf32_rna(v3);
                aH[mf][0] = __float_as_uint(h0); aL[mf][0] = __float_as_uint(tf32_rna(v0 - h0));
                aH[mf][1] = __float_as_uint(h1); aL[mf][1] = __float_as_uint(tf32_rna(v1 - h1));
                aH[mf][2] = __float_as_uint(h2); aL[mf][2] = __float_as_uint(tf32_rna(v2 - h2));
                aH[mf][3] = __float_as_uint(h3); aL[mf][3] = __float_as_uint(tf32_rna(v3 - h3));
            }
#pragma unroll
            for (int nf = 0; nf < 4; nf++) {
                int nn = wn * 32 + nf * 8 + gid;
                float w0 = B[k0 + tig][nn];
                float w1 = B[k0 + tig + 4][nn];
                float bh0f = tf32_rna(w0), bh1f = tf32_rna(w1);
                uint32_t bh0 = __float_as_uint(bh0f);
                uint32_t bh1 = __float_as_uint(bh1f);
                uint32_t bl0 = __float_as_uint(tf32_rna(w0 - bh0f));
                uint32_t bl1 = __float_as_uint(tf32_rna(w1 - bh1f));
#pragma unroll
                for (int mf = 0; mf < 4; mf++) {
                    mma_tf32(d[mf][nf], aH[mf][0], aH[mf][1], aH[mf][2], aH[mf][3], bl0, bl1);
                    mma_tf32(d[mf][nf], aL[mf][0], aL[mf][1], aL[mf][2], aL[mf][3], bh0, bh1);
                    mma_tf32(d[mf][nf], aH[mf][0], aH[mf][1], aH[mf][2], aH[mf][3], bh0, bh1);
                }
            }
        }
        buf ^= 1;
    }

    __syncthreads();
#pragma unroll
    for (int mf = 0; mf < 4; mf++) {
        int lr0 = wm * 64 + mf * 16 + gid;
#pragma unroll
        for (int nf = 0; nf < 4; nf++) {
            int lc = wn * 32 + nf * 8 + tig * 2;
            *(float2*)&sm[lr0 * TS + lc]       = make_float2(d[mf][nf][0], d[mf][nf][1]);
            *(float2*)&sm[(lr0 + 8) * TS + lc] = make_float2(d[mf][nf][2], d[mf][nf][3]);
        }
    }
    __syncthreads();

#pragma unroll
    for (int gi = 0; gi < 16; gi++) {
        int lrow = wid * 16 + gi;
        int r = row0 + lrow;
        const float* u = &sm[lrow * TS];
        const float* y0 = Brow0[lrow];
        const float* y1 = Brow1[lrow];
        float a0 = 0.f, a1 = 0.f;
#pragma unroll
        for (int it = 0; it < 4; it++) {
            int i = lane + it * 32;
            float x = u[i];
            a0 += x * y0[i];
            a1 += x * y1[i];
        }
#pragma unroll
        for (int o = 16; o; o >>= 1) {
            a0 += __shfl_xor_sync(0xffffffffu, a0, o);
            a1 += __shfl_xor_sync(0xffffffffu, a1, o);
        }
        if (lane == 0 && r < nrows) {
            float* sp = g_spart + (size_t)r * 8 + blockIdx.x * 2;
            sp[0] = a0;
            sp[1] = a1;
        }
    }
}

// ---------------------------------------------------------------------------
// K5: per cell: sum partials (fixed order) + ls/rs, select exact top-2.
__global__ __launch_bounds__(256) void fix_select_kernel(
    const float* __restrict__ chart_s, float* __restrict__ out) {
    int bl = blockIdx.x * 256 + threadIdx.x;
    if (bl >= NCELLS_BL) return;
    int b = bl / LPOS, l = bl % LPOS;
    int cbase = g_cellbase[bl];
    int cnt   = g_cellcnt[bl];

    float s1 = -INFINITY, s2 = -INFINITY;
    int z1 = 64, z2 = 64;
    for (int c = 0; c < cnt; c++) {
        int z   = g_cz[cbase + c];
        int row = g_crow[cbase + c];
        int n = z >> 2, kl = (z >> 1) & 1, kr = z & 1;
        const float* sp = g_spart + (size_t)row * 8 + kr;
        float v = ((sp[0] + sp[2]) + (sp[4] + sp[6]));
        int lcell = g_li[(l << 4) + n];
        int rcell = g_ri[(l << 4) + n];
        v += chart_s[(size_t)(kl * BATCH + b) * NCELLS + lcell];
        v += chart_s[(size_t)(kr * BATCH + b) * NCELLS + rcell];
        if (v > s1 || (v == s1 && z < z1)) {
            s2 = s1; z2 = z1; s1 = v; z1 = z;
        } else if (v > s2 || (v == s2 && z < z2)) {
            s2 = v; z2 = z;
        }
    }
    int o = bl * 2;
    out[OFF_S  + o]     = s1;
    out[OFF_S  + o + 1] = s2;
    out[OFF_N  + o]     = (float)(z1 >> 2);
    out[OFF_N  + o + 1] = (float)(z2 >> 2);
    out[OFF_LK + o]     = (float)((z1 >> 1) & 1);
    out[OFF_LK + o + 1] = (float)((z2 >> 1) & 1);
    out[OFF_RK + o]     = (float)(z1 & 1);
    out[OFF_RK + o + 1] = (float)(z2 & 1);
    g_sel[o]     = make_int4(z1 >> 2, (z1 >> 1) & 1, z1 & 1, 0);
    g_sel[o + 1] = make_int4(z2 >> 2, (z2 >> 1) & 1, z2 & 1, 0);
}

// ---------------------------------------------------------------------------
// K6: compose GEMM, 1x tf32, LDSM + 4-stage pipeline, split-K=4.
__global__ __launch_bounds__(256, 2) void gemm2_mma_kernel(
    const float* __restrict__ chart_h) {
    extern __shared__ float sm[];
    __shared__ const float* Arow[128];

    int tid  = threadIdx.x;
    int row0 = blockIdx.y * 128;
    int col0 = blockIdx.x * 128;
    int ks   = blockIdx.z;
    int kbase = ks * 256;

    if (tid < 128) {
        int r = row0 + tid;
        int bl = r >> 1;
        int b = bl / LPOS, l = bl % LPOS;
        int4 sel = g_sel[r];
        const float* base;
        if (kbase < 512) {
            int lcell = g_li[(l << 4) + sel.x];
            base = chart_h + (((size_t)(sel.y * BATCH + b)) * NCELLS + lcell) * SIZE + kbase;
        } else {
            int rcell = g_ri[(l << 4) + sel.x];
            base = chart_h + (((size_t)(sel.z * BATCH + b)) * NCELLS + rcell) * SIZE + (kbase - 512);
        }
        Arow[tid] = base;
    }
    __syncthreads();

    int cr = tid >> 1, cw = (tid & 1) * 8;
    const float* gA = Arow[cr] + cw;
    const float* gB = g_WcT + (size_t)(col0 + cr) * 1024 + kbase + cw;

    uint32_t base = (uint32_t)__cvta_generic_to_shared(sm);
    uint32_t cpA = base + (cr * TPAD + cw) * 4;
    uint32_t cpB = base + ABYTES + (cr * TPAD + cw) * 4;

    int wid = tid >> 5, lane = tid & 31;
    int wm = wid >> 2, wn = wid & 3;
    int gid = lane >> 2, tig = lane & 3;
    int t4 = lane >> 3, lr = lane & 7;

    uint32_t aAddr[4], bAddr[2];
    {
        int arow_off = (t4 & 1) * 8 + lr, acol = (t4 >> 1) * 4;
        int brow_off = ((t4 >> 1) * 8) + lr, bcol = (t4 & 1) * 4;
#pragma unroll
        for (int mf = 0; mf < 4; mf++)
            aAddr[mf] = base + ((wm * 64 + mf * 16 + arow_off) * TPAD + acol) * 4;
#pragma unroll
        for (int p = 0; p < 2; p++)
            bAddr[p] = base + ABYTES + ((wn * 32 + p * 16 + brow_off) * TPAD + bcol) * 4;
    }

    float d[4][4][4];
#pragma unroll
    for (int mf = 0; mf < 4; mf++)
#pragma unroll
        for (int nf = 0; nf < 4; nf++)
#pragma unroll
            for (int c = 0; c < 4; c++) d[mf][nf][c] = 0.f;

#pragma unroll
    for (int s = 0; s < NST - 1; s++) {
        uint32_t so = s * STAGE_BYTES;
        size_t go = (size_t)s * 16;
        CP_ASYNC16(cpA + so, gA + go);
        CP_ASYNC16(cpA + so + 16, gA + go + 4);
        CP_ASYNC16(cpB + so, gB + go);
        CP_ASYNC16(cpB + so + 16, gB + go + 4);
        CP_COMMIT();
    }

    for (int kt = 0; kt < 16; kt++) {
        CP_WAIT2();
        __syncthreads();
        int pf = kt + NST - 1;
        if (pf < 16) {
            uint32_t so = (pf & (NST - 1)) * STAGE_BYTES;
            size_t go = (size_t)pf * 16;
            CP_ASYNC16(cpA + so, gA + go);
            CP_ASYNC16(cpA + so + 16, gA + go + 4);
            CP_ASYNC16(cpB + so, gB + go);
            CP_ASYNC16(cpB + so + 16, gB + go + 4);
        }
        CP_COMMIT();

        uint32_t soff = (kt & (NST - 1)) * STAGE_BYTES;
#pragma unroll
        for (int kf = 0; kf < 2; kf++) {
            uint32_t koff = soff + kf * 32;
            uint32_t a[4][4], bb[4][2];
#pragma unroll
            for (int mf = 0; mf < 4; mf++)
                LDSM4(a[mf][0], a[mf][1], a[mf][2], a[mf][3], aAddr[mf] + koff);
#pragma unroll
            for (int p = 0; p < 2; p++)
                LDSM4(bb[2 * p][0], bb[2 * p][1], bb[2 * p + 1][0], bb[2 * p + 1][1],
                      bAddr[p] + koff);
#pragma unroll
            for (int nf = 0; nf < 4; nf++)
#pragma unroll
                for (int mf = 0; mf < 4; mf++)
                    mma_tf32(d[mf][nf], a[mf][0], a[mf][1], a[mf][2], a[mf][3],
                             bb[nf][0], bb[nf][1]);
        }
    }

#pragma unroll
    for (int mf = 0; mf < 4; mf++) {
        int rA = row0 + wm * 64 + mf * 16 + gid;
#pragma unroll
        for (int nf = 0; nf < 4; nf++) {
            int cA = col0 + wn * 32 + nf * 8 + tig * 2;
            float* p = g_P + ((size_t)ks * ROWS2 + rA) * 512 + cA;
            *(float2*)p                = make_float2(d[mf][nf][0], d[mf][nf][1]);
            *(float2*)(p + 8 * 512)    = make_float2(d[mf][nf][2], d[mf][nf][3]);
        }
    }
}

// ---------------------------------------------------------------------------
// K7: combine split-K partials + bias + tanh + unit-norm, write topk_h.
__global__ __launch_bounds__(256) void combine_normalize_kernel(
    const float* __restrict__ bc, float* __restrict__ out) {
    int r = blockIdx.x;
    int t = threadIdx.x;
    const float* p = g_P + (size_t)r * 512;
    const size_t stride = (size_t)ROWS2 * 512;

    float v0 = bc[t]       + p[t]       + p[t + stride]       + p[t + 2*stride]       + p[t + 3*stride];
    float v1 = bc[t + 256] + p[t + 256] + p[t + 256 + stride] + p[t + 256 + 2*stride] + p[t + 256 + 3*stride];
    v0 = tanhf(v0);
    v1 = tanhf(v1);

    float ss = v0 * v0 + v1 * v1;
#pragma unroll
    for (int o = 16; o; o >>= 1) ss += __shfl_xor_sync(0xffffffffu, ss, o);
    __shared__ float red[8];
    __shared__ float s_inv;
    if ((t & 31) == 0) red[t >> 5] = ss;
    __syncthreads();
    if (t == 0) {
        float x = 0.f;
#pragma unroll
        for (int i = 0; i < 8; i++) x += red[i];
        s_inv = 1.0f / sqrtf(x);
    }
    __syncthreads();
    float inv = s_inv;
    out[OFF_H + (size_t)r * 512 + t]       = v0 * inv;
    out[OFF_H + (size_t)r * 512 + t + 256] = v1 * inv;
}

// ---------------------------------------------------------------------------
extern "C" void kernel_launch(void* const* d_in, const int* in_sizes, int n_in,
                              void* d_out, int out_size) {
    const float* chart_h = (const float*)d_in[0];
    const float* chart_s = (const float*)d_in[1];
    const void*  l_index = d_in[2];
    const void*  r_index = d_in[3];
    const float* mat     = (const float*)d_in[4];
    const float* Wc      = (const float*)d_in[5];
    const float* bc      = (const float*)d_in[6];
    float* out = (float*)d_out;

    cudaFuncSetAttribute(gemm1_fused_kernel,
                         cudaFuncAttributeMaxDynamicSharedMemorySize, SMEM1);
    cudaFuncSetAttribute(rescore_gemm_kernel,
                         cudaFuncAttributeMaxDynamicSharedMemorySize, SMEM_R);
    cudaFuncSetAttribute(gemm2_mma_kernel,
                         cudaFuncAttributeMaxDynamicSharedMemorySize, SMEM_PIPE);

    prep_kernel<<<NB_PREP, 256>>>(chart_h, mat, Wc, l_index, r_index);
    gemm1_fused_kernel<<<dim3(4, ROWS1 / 128), 256, SMEM1>>>();
    nominate_kernel<<<(NCELLS_BL + 255) / 256, 256>>>(chart_s);
    rescore_gemm_kernel<<<dim3(4, MAXR / 128), 256, SMEM_R>>>(chart_h, mat);
    fix_select_kernel<<<6, 256>>>(chart_s, out);
    gemm2_mma_kernel<<<dim3(4, ROWS2 / 128, KSPLIT), 256, SMEM_PIPE>>>(chart_h);
    combine_normalize_kernel<<<ROWS2, 256>>>(bc, out);
}